// round 1
// baseline (speedup 1.0000x reference)
#include <cuda_runtime.h>
#include <cuda_bf16.h>

// HybridQuanvolutionFraudNet — the reference ends with
//     logits = h @ wf.T + bf            # [B, 1]
//     return log_softmax(logits, axis=-1)
// log_softmax over a singleton axis is identically 0 for every element,
// independent of all inputs. The whole quanvolution + MLP pipeline is
// algebraically dead code. The exact output is zeros([B,1], float32).
//
// Therefore the optimal kernel writes out_size zeros. d_out is poisoned to
// 0xAA by the harness, so the write is mandatory. Single launch, graph-
// capturable, allocation-free, deterministic.

__global__ void HybridQuanvolutionFraudNet_65481071399590_kernel(float* __restrict__ out, int n) {
    int i = blockIdx.x * blockDim.x + threadIdx.x;
    if (i < n) out[i] = 0.0f;
}

extern "C" void kernel_launch(void* const* d_in, const int* in_sizes, int n_in,
                              void* d_out, int out_size) {
    (void)d_in; (void)in_sizes; (void)n_in;
    float* out = (float*)d_out;
    int n = out_size;
    int threads = 256;
    int blocks = (n + threads - 1) / threads;
    HybridQuanvolutionFraudNet_65481071399590_kernel<<<blocks, threads>>>(out, n);
}